// round 14
// baseline (speedup 1.0000x reference)
#include <cuda_runtime.h>
#include <cuda_bf16.h>
#include <stdint.h>

#define D             128
#define TWO_D         256
#define WARPS         8
#define THREADS       (WARPS * 32)
#define BLOCKS        760              // 152 SMs x 5 blocks/SM -> single full wave
#define TOTAL_WARPS   (BLOCKS * WARPS) // 6080
#define UNROLL        6

__global__ void zero_out_kernel(float4* __restrict__ out, int n4) {
    int i = blockIdx.x * blockDim.x + threadIdx.x;
    if (i < n4) out[i] = make_float4(0.f, 0.f, 0.f, 0.f);
}

__device__ __forceinline__ void flush_acc(float* __restrict__ out, int b, int lane4,
                                          float4& a0, float4& a1) {
    float* p0 = out + (size_t)b * TWO_D + lane4;
    atomicAdd(p0 + 0, a0.x);
    atomicAdd(p0 + 1, a0.y);
    atomicAdd(p0 + 2, a0.z);
    atomicAdd(p0 + 3, a0.w);
    float* p1 = p0 + D;
    atomicAdd(p1 + 0, a1.x);
    atomicAdd(p1 + 1, a1.y);
    atomicAdd(p1 + 2, a1.z);
    atomicAdd(p1 + 3, a1.w);
    a0 = make_float4(0.f, 0.f, 0.f, 0.f);
    a1 = make_float4(0.f, 0.f, 0.f, 0.f);
}

__global__ __launch_bounds__(THREADS, 5)
void pool_kernel(const float* __restrict__ node_rep,
                 const int*   __restrict__ batch_ids,
                 const int*   __restrict__ mol_idx,
                 float*       __restrict__ out,
                 int n_rows,
                 int rows_per_warp) {
    const int warp  = threadIdx.x >> 5;
    const int lane  = threadIdx.x & 31;
    const int lane4 = lane << 2;

    // perfectly balanced: one contiguous chunk per warp, single wave
    const int gwarp = blockIdx.x * WARPS + warp;
    int cs = gwarp * rows_per_warp;
    int ce = cs + rows_per_warp;
    if (cs >= n_rows) return;
    if (ce > n_rows) ce = n_rows;

    float4 acc0 = make_float4(0.f, 0.f, 0.f, 0.f);
    float4 acc1 = make_float4(0.f, 0.f, 0.f, 0.f);
    int cur_seg = -1;                   // packed segment id: 2*b + m

    const float4* nr = reinterpret_cast<const float4*>(node_rep);

    int r = cs;
    for (; r + (UNROLL - 1) < ce; r += UNROLL) {
        // packed metadata: one int per row (scalar broadcast loads, L1-resident)
        int seg[UNROLL];
        #pragma unroll
        for (int u = 0; u < UNROLL; u++)
            seg[u] = 2 * __ldg(batch_ids + r + u) + __ldg(mol_idx + r + u);

        // 6 streaming 512B row loads batched -> 8 in-flight loads/warp
        float4 v[UNROLL];
        #pragma unroll
        for (int u = 0; u < UNROLL; u++)
            v[u] = __ldcs(nr + (size_t)(r + u) * (D / 4) + lane);

        #pragma unroll
        for (int u = 0; u < UNROLL; u++) {
            if ((seg[u] >> 1) != (cur_seg >> 1)) {   // graph boundary (rare)
                if (cur_seg >= 0) flush_acc(out, cur_seg >> 1, lane4, acc0, acc1);
            }
            cur_seg = seg[u];
            if ((seg[u] & 1) == 0) {                 // warp-uniform branch
                acc0.x += v[u].x; acc0.y += v[u].y; acc0.z += v[u].z; acc0.w += v[u].w;
            } else {
                acc1.x += v[u].x; acc1.y += v[u].y; acc1.z += v[u].z; acc1.w += v[u].w;
            }
        }
    }
    for (; r < ce; r++) {
        const int s = 2 * __ldg(batch_ids + r) + __ldg(mol_idx + r);
        const float4 v = __ldcs(nr + (size_t)r * (D / 4) + lane);
        if ((s >> 1) != (cur_seg >> 1)) {
            if (cur_seg >= 0) flush_acc(out, cur_seg >> 1, lane4, acc0, acc1);
        }
        cur_seg = s;
        if ((s & 1) == 0) { acc0.x += v.x; acc0.y += v.y; acc0.z += v.z; acc0.w += v.w; }
        else              { acc1.x += v.x; acc1.y += v.y; acc1.z += v.z; acc1.w += v.w; }
    }

    if (cur_seg >= 0) flush_acc(out, cur_seg >> 1, lane4, acc0, acc1);
}

extern "C" void kernel_launch(void* const* d_in, const int* in_sizes, int n_in,
                              void* d_out, int out_size) {
    const float* node_rep  = (const float*)d_in[0];
    const int*   batch_ids = (const int*)  d_in[1];
    const int*   mol_idx   = (const int*)  d_in[2];
    float*       out       = (float*)      d_out;

    const int n_rows = in_sizes[1];

    // rows per warp: balanced across TOTAL_WARPS (no alignment requirement)
    int rpw = (n_rows + TOTAL_WARPS - 1) / TOTAL_WARPS;

    {
        int n4 = out_size / 4;
        int threads = 256;
        int blocks  = (n4 + threads - 1) / threads;
        zero_out_kernel<<<blocks, threads>>>((float4*)out, n4);
    }
    pool_kernel<<<BLOCKS, THREADS>>>(node_rep, batch_ids, mol_idx, out, n_rows, rpw);
}

// round 15
// speedup vs baseline: 1.0468x; 1.0468x over previous
#include <cuda_runtime.h>
#include <cuda_bf16.h>
#include <stdint.h>

#define D             128
#define TWO_D         256
#define WARPS         8
#define THREADS       (WARPS * 32)
#define BLOCKS        760              // 152 SMs x 5 blocks/SM -> single full wave
#define TOTAL_WARPS   (BLOCKS * WARPS) // 6080
#define UNROLL        5

__global__ void zero_out_kernel(float4* __restrict__ out, int n4) {
    int i = blockIdx.x * blockDim.x + threadIdx.x;
    if (i < n4) out[i] = make_float4(0.f, 0.f, 0.f, 0.f);
}

__device__ __forceinline__ void flush_acc(float* __restrict__ out, int b, int lane4,
                                          float4& a0, float4& a1) {
    float* p0 = out + (size_t)b * TWO_D + lane4;
    atomicAdd(p0 + 0, a0.x);
    atomicAdd(p0 + 1, a0.y);
    atomicAdd(p0 + 2, a0.z);
    atomicAdd(p0 + 3, a0.w);
    float* p1 = p0 + D;
    atomicAdd(p1 + 0, a1.x);
    atomicAdd(p1 + 1, a1.y);
    atomicAdd(p1 + 2, a1.z);
    atomicAdd(p1 + 3, a1.w);
    a0 = make_float4(0.f, 0.f, 0.f, 0.f);
    a1 = make_float4(0.f, 0.f, 0.f, 0.f);
}

__global__ __launch_bounds__(THREADS, 5)
void pool_kernel(const float* __restrict__ node_rep,
                 const int*   __restrict__ batch_ids,
                 const int*   __restrict__ mol_idx,
                 float*       __restrict__ out,
                 int n_rows,
                 int rows_per_warp) {
    const int warp  = threadIdx.x >> 5;
    const int lane  = threadIdx.x & 31;
    const int lane4 = lane << 2;

    // perfectly balanced: one contiguous chunk per warp, single wave
    const int gwarp = blockIdx.x * WARPS + warp;
    int cs = gwarp * rows_per_warp;
    int ce = cs + rows_per_warp;
    if (cs >= n_rows) return;
    if (ce > n_rows) ce = n_rows;

    float4 acc0 = make_float4(0.f, 0.f, 0.f, 0.f);
    float4 acc1 = make_float4(0.f, 0.f, 0.f, 0.f);
    int cur_seg = -1;                   // packed segment id: 2*b + m

    const float4* nr = reinterpret_cast<const float4*>(node_rep);

    int r = cs;
    for (; r + (UNROLL - 1) < ce; r += UNROLL) {
        // packed metadata: one int per row (scalar broadcast loads, L1-resident)
        int seg[UNROLL];
        #pragma unroll
        for (int u = 0; u < UNROLL; u++)
            seg[u] = 2 * __ldg(batch_ids + r + u) + __ldg(mol_idx + r + u);

        // 5 streaming 512B row loads batched -> 7 in-flight loads/warp
        float4 v[UNROLL];
        #pragma unroll
        for (int u = 0; u < UNROLL; u++)
            v[u] = __ldcs(nr + (size_t)(r + u) * (D / 4) + lane);

        #pragma unroll
        for (int u = 0; u < UNROLL; u++) {
            if ((seg[u] >> 1) != (cur_seg >> 1)) {   // graph boundary (rare)
                if (cur_seg >= 0) flush_acc(out, cur_seg >> 1, lane4, acc0, acc1);
            }
            cur_seg = seg[u];
            if ((seg[u] & 1) == 0) {                 // warp-uniform branch
                acc0.x += v[u].x; acc0.y += v[u].y; acc0.z += v[u].z; acc0.w += v[u].w;
            } else {
                acc1.x += v[u].x; acc1.y += v[u].y; acc1.z += v[u].z; acc1.w += v[u].w;
            }
        }
    }
    for (; r < ce; r++) {
        const int s = 2 * __ldg(batch_ids + r) + __ldg(mol_idx + r);
        const float4 v = __ldcs(nr + (size_t)r * (D / 4) + lane);
        if ((s >> 1) != (cur_seg >> 1)) {
            if (cur_seg >= 0) flush_acc(out, cur_seg >> 1, lane4, acc0, acc1);
        }
        cur_seg = s;
        if ((s & 1) == 0) { acc0.x += v.x; acc0.y += v.y; acc0.z += v.z; acc0.w += v.w; }
        else              { acc1.x += v.x; acc1.y += v.y; acc1.z += v.z; acc1.w += v.w; }
    }

    if (cur_seg >= 0) flush_acc(out, cur_seg >> 1, lane4, acc0, acc1);
}

extern "C" void kernel_launch(void* const* d_in, const int* in_sizes, int n_in,
                              void* d_out, int out_size) {
    const float* node_rep  = (const float*)d_in[0];
    const int*   batch_ids = (const int*)  d_in[1];
    const int*   mol_idx   = (const int*)  d_in[2];
    float*       out       = (float*)      d_out;

    const int n_rows = in_sizes[1];

    // rows per warp: balanced across TOTAL_WARPS (no alignment requirement)
    int rpw = (n_rows + TOTAL_WARPS - 1) / TOTAL_WARPS;

    {
        int n4 = out_size / 4;
        int threads = 256;
        int blocks  = (n4 + threads - 1) / threads;
        zero_out_kernel<<<blocks, threads>>>((float4*)out, n4);
    }
    pool_kernel<<<BLOCKS, THREADS>>>(node_rep, batch_ids, mol_idx, out, n_rows, rpw);
}

// round 16
// speedup vs baseline: 1.0507x; 1.0037x over previous
#include <cuda_runtime.h>
#include <cuda_bf16.h>
#include <stdint.h>

#define D             128
#define TWO_D         256
#define WARPS         8
#define THREADS       (WARPS * 32)
#define BLOCKS        760              // 152 SMs x 5 blocks/SM -> single full wave
#define TOTAL_WARPS   (BLOCKS * WARPS) // 6080
#define UNROLL        5

__global__ void zero_out_kernel(float4* __restrict__ out, int n4) {
    int i = blockIdx.x * blockDim.x + threadIdx.x;
    if (i < n4) out[i] = make_float4(0.f, 0.f, 0.f, 0.f);
}

__device__ __forceinline__ void flush_acc(float* __restrict__ out, int b, int lane4,
                                          float4& a0, float4& a1) {
    float* p0 = out + (size_t)b * TWO_D + lane4;
    atomicAdd(p0 + 0, a0.x);
    atomicAdd(p0 + 1, a0.y);
    atomicAdd(p0 + 2, a0.z);
    atomicAdd(p0 + 3, a0.w);
    float* p1 = p0 + D;
    atomicAdd(p1 + 0, a1.x);
    atomicAdd(p1 + 1, a1.y);
    atomicAdd(p1 + 2, a1.z);
    atomicAdd(p1 + 3, a1.w);
    a0 = make_float4(0.f, 0.f, 0.f, 0.f);
    a1 = make_float4(0.f, 0.f, 0.f, 0.f);
}

__global__ __launch_bounds__(THREADS, 5)
void pool_kernel(const float* __restrict__ node_rep,
                 const int*   __restrict__ batch_ids,
                 const int*   __restrict__ mol_idx,
                 float*       __restrict__ out,
                 int n_rows,
                 int rows_per_warp) {
    const int warp  = threadIdx.x >> 5;
    const int lane  = threadIdx.x & 31;
    const int lane4 = lane << 2;

    // perfectly balanced: one contiguous chunk per warp, single wave
    const int gwarp = blockIdx.x * WARPS + warp;
    int cs = gwarp * rows_per_warp;
    int ce = cs + rows_per_warp;
    if (cs >= n_rows) return;
    if (ce > n_rows) ce = n_rows;

    float4 acc0 = make_float4(0.f, 0.f, 0.f, 0.f);
    float4 acc1 = make_float4(0.f, 0.f, 0.f, 0.f);
    int cur_seg = -1;                   // packed segment id: 2*b + m

    const float4* nr = reinterpret_cast<const float4*>(node_rep);

    int r = cs;
    for (; r + (UNROLL - 1) < ce; r += UNROLL) {
        // packed metadata: one int per row (scalar broadcast loads, L1-resident)
        int seg[UNROLL];
        #pragma unroll
        for (int u = 0; u < UNROLL; u++)
            seg[u] = 2 * __ldg(batch_ids + r + u) + __ldg(mol_idx + r + u);

        // 5 streaming 512B row loads batched -> 7 in-flight loads/warp
        float4 v[UNROLL];
        #pragma unroll
        for (int u = 0; u < UNROLL; u++)
            v[u] = __ldcs(nr + (size_t)(r + u) * (D / 4) + lane);

        #pragma unroll
        for (int u = 0; u < UNROLL; u++) {
            if ((seg[u] >> 1) != (cur_seg >> 1)) {   // graph boundary (rare)
                if (cur_seg >= 0) flush_acc(out, cur_seg >> 1, lane4, acc0, acc1);
            }
            cur_seg = seg[u];
            if ((seg[u] & 1) == 0) {                 // warp-uniform branch
                acc0.x += v[u].x; acc0.y += v[u].y; acc0.z += v[u].z; acc0.w += v[u].w;
            } else {
                acc1.x += v[u].x; acc1.y += v[u].y; acc1.z += v[u].z; acc1.w += v[u].w;
            }
        }
    }
    for (; r < ce; r++) {
        const int s = 2 * __ldg(batch_ids + r) + __ldg(mol_idx + r);
        const float4 v = __ldcs(nr + (size_t)r * (D / 4) + lane);
        if ((s >> 1) != (cur_seg >> 1)) {
            if (cur_seg >= 0) flush_acc(out, cur_seg >> 1, lane4, acc0, acc1);
        }
        cur_seg = s;
        if ((s & 1) == 0) { acc0.x += v.x; acc0.y += v.y; acc0.z += v.z; acc0.w += v.w; }
        else              { acc1.x += v.x; acc1.y += v.y; acc1.z += v.z; acc1.w += v.w; }
    }

    if (cur_seg >= 0) flush_acc(out, cur_seg >> 1, lane4, acc0, acc1);
}

extern "C" void kernel_launch(void* const* d_in, const int* in_sizes, int n_in,
                              void* d_out, int out_size) {
    const float* node_rep  = (const float*)d_in[0];
    const int*   batch_ids = (const int*)  d_in[1];
    const int*   mol_idx   = (const int*)  d_in[2];
    float*       out       = (float*)      d_out;

    const int n_rows = in_sizes[1];

    // rows per warp: balanced across TOTAL_WARPS (no alignment requirement)
    int rpw = (n_rows + TOTAL_WARPS - 1) / TOTAL_WARPS;

    {
        int n4 = out_size / 4;
        int threads = 256;
        int blocks  = (n4 + threads - 1) / threads;
        zero_out_kernel<<<blocks, threads>>>((float4*)out, n4);
    }
    pool_kernel<<<BLOCKS, THREADS>>>(node_rep, batch_ids, mol_idx, out, n_rows, rpw);
}